// round 7
// baseline (speedup 1.0000x reference)
#include <cuda_runtime.h>
#include <cuda_bf16.h>
#include <cstdint>

#define NEVT 8192
#define NSEVT 16384
#define DIM 128

// ---------------- scratch (__device__ globals: no allocation allowed) -----
__device__ float g_sproj[NSEVT];                       // s_proj * log2(e)
__device__ float g_eproj[NEVT];                        // e_proj * log2(e)
// subevent^T in bf16, TILE-MAJOR: [ktile = j/64][d = 0..127][j%64]
__device__ __nv_bfloat16 g_ST[(size_t)DIM * NSEVT];
__device__ float g_num[2ull * NEVT * DIM];             // split-K numerator partials
__device__ float g_z[2 * NEVT];                        // split-K Z partials

// ---------------- helpers ---------------------------------------------------
__device__ __forceinline__ uint32_t smem_u32(const void* p) {
    uint32_t a;
    asm("{ .reg .u64 t; cvta.to.shared.u64 t, %1; cvt.u32.u64 %0, t; }"
        : "=r"(a) : "l"(p));
    return a;
}

__device__ __forceinline__ uint32_t pack_bf16x2(float lo, float hi) {
    uint32_t r;
    asm("cvt.rn.bf16x2.f32 %0, %1, %2;" : "=r"(r) : "f"(hi), "f"(lo));
    return r;
}

__device__ __forceinline__ float ex2f(float x) {   // 2^x
    float y;
    asm("ex2.approx.ftz.f32 %0, %1;" : "=f"(y) : "f"(x));
    return y;
}

__device__ __forceinline__ void ldm_x4(uint32_t addr, uint32_t* r) {
    asm volatile("ldmatrix.sync.aligned.m8n8.x4.shared.b16 {%0,%1,%2,%3}, [%4];"
                 : "=r"(r[0]), "=r"(r[1]), "=r"(r[2]), "=r"(r[3]) : "r"(addr));
}

__device__ __forceinline__ void mma16816(float* d, const uint32_t* a, const uint32_t* b) {
    asm volatile(
        "mma.sync.aligned.m16n8k16.row.col.f32.bf16.bf16.f32 "
        "{%0,%1,%2,%3}, {%4,%5,%6,%7}, {%8,%9}, {%0,%1,%2,%3};"
        : "+f"(d[0]), "+f"(d[1]), "+f"(d[2]), "+f"(d[3])
        : "r"(a[0]), "r"(a[1]), "r"(a[2]), "r"(a[3]), "r"(b[0]), "r"(b[1]));
}

__device__ __forceinline__ void mbar_init(uint32_t a, uint32_t cnt) {
    asm volatile("mbarrier.init.shared.b64 [%0], %1;" :: "r"(a), "r"(cnt) : "memory");
}
__device__ __forceinline__ void mbar_arrive(uint32_t a) {
    asm volatile("mbarrier.arrive.shared.b64 _, [%0];" :: "r"(a) : "memory");
}
__device__ __forceinline__ void mbar_wait(uint32_t a, uint32_t parity) {
    asm volatile(
        "{\n\t.reg .pred P;\n\t"
        "WAITLP_%=:\n\t"
        "mbarrier.try_wait.parity.acquire.cta.shared::cta.b64 P, [%0], %1, 0x989680;\n\t"
        "@P bra.uni WAITDN_%=;\n\t"
        "bra.uni WAITLP_%=;\n\t"
        "WAITDN_%=:\n\t}"
        :: "r"(a), "r"(parity) : "memory");
}

__device__ __forceinline__ void cp_async16(uint32_t dst, const void* src) {
    asm volatile("cp.async.cg.shared.global [%0], [%1], 16;"
                 :: "r"(dst), "l"(src) : "memory");
}
__device__ __forceinline__ void cp_async_commit() {
    asm volatile("cp.async.commit_group;" ::: "memory");
}
__device__ __forceinline__ void cp_async_wait0() {
    asm volatile("cp.async.wait_group 0;" ::: "memory");
}

// ---------------- kernel 1: projections (scaled by log2 e) ------------------
__global__ void proj_kernel(const float* __restrict__ sub,
                            const float* __restrict__ evt,
                            const float* __restrict__ w) {
    const float L = 1.4426950408889634f;
    int gw = (blockIdx.x * blockDim.x + threadIdx.x) >> 5;
    int lane = threadIdx.x & 31;
    int nw = (gridDim.x * blockDim.x) >> 5;
    for (int r = gw; r < NSEVT + NEVT; r += nw) {
        const float* base;
        const float* wp;
        if (r < NSEVT) { base = sub + (size_t)r * DIM; wp = w; }
        else           { base = evt + (size_t)(r - NSEVT) * DIM; wp = w + DIM; }
        float4 v = ((const float4*)base)[lane];
        float4 ww = __ldg((const float4*)wp + lane);
        float d = v.x * ww.x + v.y * ww.y + v.z * ww.z + v.w * ww.w;
        #pragma unroll
        for (int o = 16; o; o >>= 1) d += __shfl_xor_sync(0xffffffffu, d, o);
        if (lane == 0) {
            if (r < NSEVT) g_sproj[r] = d * L;
            else           g_eproj[r - NSEVT] = d * L;
        }
    }
}

// ---------------- kernel 2: subevent -> bf16 transpose, tile-major ----------
__global__ void transpose_kernel(const float* __restrict__ sub) {
    __shared__ __nv_bfloat16 smT[128][72];  // 144B rows
    int t = threadIdx.x;                    // 256 threads
    int j0 = blockIdx.x * 64;               // this block's 64 j's (one k-tile)
    int jl = t >> 2;
    int sbase = t & 3;
    const float4* src = (const float4*)(sub + (size_t)(j0 + jl) * DIM);
    #pragma unroll
    for (int it = 0; it < 8; ++it) {
        int s = sbase + it * 4;
        float4 v = src[s];
        int d = s * 4;
        smT[d + 0][jl] = __float2bfloat16(v.x);
        smT[d + 1][jl] = __float2bfloat16(v.y);
        smT[d + 2][jl] = __float2bfloat16(v.z);
        smT[d + 3][jl] = __float2bfloat16(v.w);
    }
    __syncthreads();
    int d = t >> 1;
    int jh = (t & 1) * 32;
    uint4* dst = (uint4*)(g_ST + (size_t)blockIdx.x * (128 * 64) + d * 64 + jh);
    const uint4* s4 = (const uint4*)&smT[d][jh];
    dst[0] = s4[0]; dst[1] = s4[1]; dst[2] = s4[2]; dst[3] = s4[3];
}

// ---------------- kernel 3: warp-specialized fused softmax-GEMM -------------
// grid 128 (64 row-tiles x 2 k-halves), 512 threads.
// warps 0-7: consumers (ldmatrix + mma, ks-pipelined).
// warps 8-15: producers (adj stream, exp, cp.async B, Z accumulation).
// smem layout:
//   [0, 32768)          sproj half (8192 floats)
//   [32768, 32832)      mbarriers: {full[s], empty[s]} interleaved, s<4
//   [33024 + s*36864)   stage s: A tile 18432B (128 x 144B), B tile 18432B
#define SP_OFF   0
#define BAR_OFF  32768
#define ST_OFF   33024
#define STAGE_SZ 36864
#define A_SZ     18432
#define NSTAGE   4
#define SMEM_BYTES (ST_OFF + NSTAGE * STAGE_SZ)

__global__ void __launch_bounds__(512, 1)
main_kernel(const float* __restrict__ adj) {
    extern __shared__ char smem[];
    const int tid = threadIdx.x;
    const int wid = tid >> 5;
    const int lid = tid & 31;

    const int tile = blockIdx.x >> 1;
    const int kv_half = blockIdx.x & 1;
    const int i0 = tile * 128;
    const int k0 = kv_half * (NSEVT / 2);

    const uint32_t sb = smem_u32(smem);

    // cooperative sproj load (all 512 threads)
    {
        float4* spd = (float4*)(smem + SP_OFF);
        const float4* sps = (const float4*)(g_sproj + k0);
        for (int i = tid; i < 2048; i += 512) spd[i] = __ldg(sps + i);
    }
    if (tid == 0) {
        #pragma unroll
        for (int s = 0; s < NSTAGE; ++s) {
            mbar_init(sb + BAR_OFF + s * 16, 256);      // full[s]: 256 producers
            mbar_init(sb + BAR_OFF + s * 16 + 8, 256);  // empty[s]: 256 consumers
        }
    }
    __syncthreads();

    if (wid >= 8) {
        // =================== PRODUCER ===================
        const int ptid = tid - 256;
        const int row = ptid >> 1;
        const int hk = ptid & 1;
        const float ep = g_eproj[i0 + row];
        const float4* a4p = (const float4*)(adj + (size_t)(i0 + row) * NSEVT + k0);
        const char* stb = (const char*)(g_ST + (size_t)(kv_half * 128) * (128 * 64)
                                             + row * 64 + hk * 32);
        const float4* sp4 = (const float4*)(smem + SP_OFF);
        const uint32_t arow = (uint32_t)row * 144u;

        float zacc = 0.f;
        float4 areg[2][8];
        #pragma unroll
        for (int it = 0; it < 8; ++it) areg[0][it] = __ldg(a4p + (hk + 2 * it));

        int st = 0, ph = 1;   // producer parity starts at 1: first empty-wait passes

        for (int kt = 0; kt < 128; ++kt) {
            const int cur = kt & 1;

            // wait stage free (4-deep ring: usually fast-path)
            mbar_wait(sb + BAR_OFF + st * 16 + 8, ph);

            const uint32_t Ab = sb + ST_OFF + (uint32_t)st * STAGE_SZ;

            // B tile: cp.async straight to smem (no registers)
            {
                const char* bsrc = stb + (size_t)kt * (128 * 64 * 2);
                uint32_t Brow = Ab + A_SZ + arow + (uint32_t)hk * 64u;
                #pragma unroll
                for (int j = 0; j < 4; ++j) cp_async16(Brow + j * 16, bsrc + j * 16);
                cp_async_commit();
            }

            // adj prefetch for next tile (consumed ~1 tile later)
            if (kt < 127) {
                const float4* anext = a4p + (kt + 1) * 16;
                #pragma unroll
                for (int it = 0; it < 8; ++it)
                    areg[cur ^ 1][it] = __ldg(anext + (hk + 2 * it));
            }

            // exp compute, store W directly to stage (stage already free)
            #pragma unroll
            for (int it = 0; it < 8; ++it) {
                const int slot = hk + 2 * it;
                float4 a = areg[cur][it];
                float4 s = sp4[kt * 16 + slot];
                float c0 = ep + s.x, c1 = ep + s.y, c2 = ep + s.z, c3 = ep + s.w;
                float f0 = fmaxf(c0, 0.2f * c0), f1 = fmaxf(c1, 0.2f * c1);
                float f2 = fmaxf(c2, 0.2f * c2), f3 = fmaxf(c3, 0.2f * c3);
                float e0 = ex2f(a.x * f0), e1 = ex2f(a.y * f1);
                float e2 = ex2f(a.z * f2), e3 = ex2f(a.w * f3);
                zacc += (e0 + e1) + (e2 + e3);
                uint32_t p0 = pack_bf16x2(e0 * a.x, e1 * a.y);
                uint32_t p1 = pack_bf16x2(e2 * a.z, e3 * a.w);
                *reinterpret_cast<uint2*>(smem + (Ab - sb) + arow + slot * 8) =
                    make_uint2(p0, p1);
            }

            cp_async_wait0();                      // B landed
            mbar_arrive(sb + BAR_OFF + st * 16);   // publish full[st]

            if (++st == NSTAGE) { st = 0; ph ^= 1; }
        }

        // Z partial
        zacc += __shfl_xor_sync(0xffffffffu, zacc, 1);
        if (hk == 0) g_z[(size_t)kv_half * NEVT + i0 + row] = zacc;

    } else {
        // =================== CONSUMER ===================
        const int m0 = (wid & 3) * 32;
        const int n0 = (wid >> 2) * 64;
        const uint32_t a_radd = (uint32_t)(lid & 15) * 144u + ((uint32_t)(lid >> 4) * 8u) * 2u;
        const uint32_t b_radd = ((uint32_t)(lid & 7) + ((uint32_t)(lid >> 4) & 1u) * 8u) * 144u
                              + (((uint32_t)(lid >> 3) & 1u) * 8u) * 2u;
        const uint32_t aoff0 = (uint32_t)m0 * 144u + a_radd;
        const uint32_t aoff1 = (uint32_t)(m0 + 16) * 144u + a_radd;

        float acc[2][8][4];
        #pragma unroll
        for (int mt = 0; mt < 2; ++mt)
            #pragma unroll
            for (int nb = 0; nb < 8; ++nb)
                #pragma unroll
                for (int q = 0; q < 4; ++q) acc[mt][nb][q] = 0.f;

        int st = 0, ph = 0;

        for (int kt = 0; kt < 128; ++kt) {
            mbar_wait(sb + BAR_OFF + st * 16, ph);   // full[st]

            const uint32_t Asb = sb + ST_OFF + (uint32_t)st * STAGE_SZ;
            const uint32_t Bsb = Asb + A_SZ;

            uint32_t frA[2][4];
            uint32_t frB[2][8][2];

            // preload B fragments for ks=0
            #pragma unroll
            for (int q = 0; q < 4; ++q) {
                uint32_t t[4];
                ldm_x4(Bsb + (uint32_t)(n0 + 16 * q) * 144u + b_radd, t);
                frB[0][2 * q][0] = t[0]; frB[0][2 * q][1] = t[1];
                frB[0][2 * q + 1][0] = t[2]; frB[0][2 * q + 1][1] = t[3];
            }

            #pragma unroll
            for (int ks = 0; ks < 4; ++ks) {
                const int b = ks & 1;
                // A fragments for this ks
                ldm_x4(Asb + aoff0 + (uint32_t)(ks * 32), frA[0]);
                ldm_x4(Asb + aoff1 + (uint32_t)(ks * 32), frA[1]);
                // prefetch B fragments for next ks
                if (ks < 3) {
                    #pragma unroll
                    for (int q = 0; q < 4; ++q) {
                        uint32_t t[4];
                        ldm_x4(Bsb + (uint32_t)(n0 + 16 * q) * 144u
                                   + (uint32_t)((ks + 1) * 32) + b_radd, t);
                        frB[b ^ 1][2 * q][0] = t[0]; frB[b ^ 1][2 * q][1] = t[1];
                        frB[b ^ 1][2 * q + 1][0] = t[2]; frB[b ^ 1][2 * q + 1][1] = t[3];
                    }
                }
                #pragma unroll
                for (int mt = 0; mt < 2; ++mt)
                    #pragma unroll
                    for (int nb = 0; nb < 8; ++nb)
                        mma16816(acc[mt][nb], frA[mt], frB[b][nb]);
            }

            mbar_arrive(sb + BAR_OFF + st * 16 + 8);  // empty[st]
            if (++st == NSTAGE) { st = 0; ph ^= 1; }
        }

        // numerator partial writeout
        float* base = g_num + (size_t)kv_half * NEVT * DIM;
        const int r01 = i0 + m0 + (lid >> 2);
        const int colb = n0 + (lid & 3) * 2;
        #pragma unroll
        for (int mt = 0; mt < 2; ++mt) {
            #pragma unroll
            for (int nb = 0; nb < 8; ++nb) {
                int rr = r01 + mt * 16;
                int cc = colb + nb * 8;
                float2 lo = make_float2(acc[mt][nb][0], acc[mt][nb][1]);
                float2 hi = make_float2(acc[mt][nb][2], acc[mt][nb][3]);
                *reinterpret_cast<float2*>(base + (size_t)rr * DIM + cc) = lo;
                *reinterpret_cast<float2*>(base + (size_t)(rr + 8) * DIM + cc) = hi;
            }
        }
    }
}

// ---------------- kernel 4: combine split-K + epilogue ----------------------
__global__ void finalize_kernel(const float* __restrict__ evt, float* __restrict__ out) {
    int idx = blockIdx.x * blockDim.x + threadIdx.x;   // float4 index
    if (idx >= NEVT * (DIM / 4)) return;
    int i = idx >> 5;                                   // row
    float z = g_z[i] + g_z[NEVT + i];
    float inv = 1.0f / z;
    float4 n0 = *((const float4*)g_num + idx);
    float4 n1 = *((const float4*)g_num + (size_t)NEVT * (DIM / 4) + idx);
    float4 e = __ldg((const float4*)evt + idx);
    float4 o;
    o.x = (e.x + (n0.x + n1.x) * inv) * 0.5f;
    o.y = (e.y + (n0.y + n1.y) * inv) * 0.5f;
    o.z = (e.z + (n0.z + n1.z) * inv) * 0.5f;
    o.w = (e.w + (n0.w + n1.w) * inv) * 0.5f;
    ((float4*)out)[idx] = o;
}

// ---------------- launch ----------------------------------------------------
extern "C" void kernel_launch(void* const* d_in, const int* in_sizes, int n_in,
                              void* d_out, int out_size) {
    const float *adj = nullptr, *sub = nullptr, *evt = nullptr, *w = nullptr;
    for (int i = 0; i < n_in; ++i) {
        switch (in_sizes[i]) {
            case NEVT * NSEVT: adj = (const float*)d_in[i]; break;
            case NSEVT * DIM:  sub = (const float*)d_in[i]; break;
            case NEVT * DIM:   evt = (const float*)d_in[i]; break;
            case 2 * DIM:      w   = (const float*)d_in[i]; break;
            default: break;
        }
    }
    (void)out_size;

    static int configured = 0;
    if (!configured) {
        cudaFuncSetAttribute(main_kernel, cudaFuncAttributeMaxDynamicSharedMemorySize,
                             SMEM_BYTES);
        configured = 1;
    }

    proj_kernel<<<96, 256>>>(sub, evt, w);
    transpose_kernel<<<256, 256>>>(sub);
    main_kernel<<<128, 512, SMEM_BYTES>>>(adj);
    finalize_kernel<<<(NEVT * (DIM / 4) + 255) / 256, 256>>>(evt, (float*)d_out);
}

// round 8
// speedup vs baseline: 1.8438x; 1.8438x over previous
#include <cuda_runtime.h>
#include <cuda_bf16.h>
#include <cstdint>

#define NEVT 8192
#define NSEVT 16384
#define DIM 128

// ---------------- scratch (__device__ globals: no allocation allowed) -----
__device__ float g_sproj[NSEVT];                       // s_proj * log2(e)
__device__ float g_eproj[NEVT];                        // e_proj * log2(e)
// subevent^T in bf16, TILE-MAJOR: [ktile = j/64][d = 0..127][j%64]
__device__ __nv_bfloat16 g_ST[(size_t)DIM * NSEVT];
__device__ float g_num[2ull * NEVT * DIM];             // split-K numerator partials
__device__ float g_z[2 * NEVT];                        // split-K Z partials

// ---------------- helpers ---------------------------------------------------
__device__ __forceinline__ uint32_t smem_u32(const void* p) {
    uint32_t a;
    asm("{ .reg .u64 t; cvta.to.shared.u64 t, %1; cvt.u32.u64 %0, t; }"
        : "=r"(a) : "l"(p));
    return a;
}

__device__ __forceinline__ uint32_t pack_bf16x2(float lo, float hi) {
    uint32_t r;
    asm("cvt.rn.bf16x2.f32 %0, %1, %2;" : "=r"(r) : "f"(hi), "f"(lo));
    return r;
}

__device__ __forceinline__ float ex2f(float x) {   // 2^x
    float y;
    asm("ex2.approx.ftz.f32 %0, %1;" : "=f"(y) : "f"(x));
    return y;
}

__device__ __forceinline__ void ldm_x4(uint32_t addr, uint32_t* r) {
    asm volatile("ldmatrix.sync.aligned.m8n8.x4.shared.b16 {%0,%1,%2,%3}, [%4];"
                 : "=r"(r[0]), "=r"(r[1]), "=r"(r[2]), "=r"(r[3]) : "r"(addr));
}

__device__ __forceinline__ void mma16816(float* d, const uint32_t* a, const uint32_t* b) {
    asm volatile(
        "mma.sync.aligned.m16n8k16.row.col.f32.bf16.bf16.f32 "
        "{%0,%1,%2,%3}, {%4,%5,%6,%7}, {%8,%9}, {%0,%1,%2,%3};"
        : "+f"(d[0]), "+f"(d[1]), "+f"(d[2]), "+f"(d[3])
        : "r"(a[0]), "r"(a[1]), "r"(a[2]), "r"(a[3]), "r"(b[0]), "r"(b[1]));
}

__device__ __forceinline__ void mbar_init(uint32_t a, uint32_t cnt) {
    asm volatile("mbarrier.init.shared.b64 [%0], %1;" :: "r"(a), "r"(cnt) : "memory");
}
__device__ __forceinline__ void mbar_arrive(uint32_t a) {
    asm volatile("mbarrier.arrive.shared.b64 _, [%0];" :: "r"(a) : "memory");
}
__device__ __forceinline__ void mbar_wait(uint32_t a, uint32_t parity) {
    asm volatile(
        "{\n\t.reg .pred P;\n\t"
        "WAITLP_%=:\n\t"
        "mbarrier.try_wait.parity.acquire.cta.shared::cta.b64 P, [%0], %1, 0x989680;\n\t"
        "@P bra.uni WAITDN_%=;\n\t"
        "bra.uni WAITLP_%=;\n\t"
        "WAITDN_%=:\n\t}"
        :: "r"(a), "r"(parity) : "memory");
}

// ---------------- kernel 1: projections (scaled by log2 e) ------------------
__global__ void proj_kernel(const float* __restrict__ sub,
                            const float* __restrict__ evt,
                            const float* __restrict__ w) {
    const float L = 1.4426950408889634f;
    int gw = (blockIdx.x * blockDim.x + threadIdx.x) >> 5;
    int lane = threadIdx.x & 31;
    int nw = (gridDim.x * blockDim.x) >> 5;
    for (int r = gw; r < NSEVT + NEVT; r += nw) {
        const float* base;
        const float* wp;
        if (r < NSEVT) { base = sub + (size_t)r * DIM; wp = w; }
        else           { base = evt + (size_t)(r - NSEVT) * DIM; wp = w + DIM; }
        float4 v = ((const float4*)base)[lane];
        float4 ww = __ldg((const float4*)wp + lane);
        float d = v.x * ww.x + v.y * ww.y + v.z * ww.z + v.w * ww.w;
        #pragma unroll
        for (int o = 16; o; o >>= 1) d += __shfl_xor_sync(0xffffffffu, d, o);
        if (lane == 0) {
            if (r < NSEVT) g_sproj[r] = d * L;
            else           g_eproj[r - NSEVT] = d * L;
        }
    }
}

// ---------------- kernel 2: subevent -> bf16 transpose, tile-major ----------
__global__ void transpose_kernel(const float* __restrict__ sub) {
    __shared__ __nv_bfloat16 smT[128][72];  // 144B rows
    int t = threadIdx.x;                    // 256 threads
    int j0 = blockIdx.x * 64;               // this block's 64 j's (one k-tile)
    int jl = t >> 2;
    int sbase = t & 3;
    const float4* src = (const float4*)(sub + (size_t)(j0 + jl) * DIM);
    #pragma unroll
    for (int it = 0; it < 8; ++it) {
        int s = sbase + it * 4;
        float4 v = src[s];
        int d = s * 4;
        smT[d + 0][jl] = __float2bfloat16(v.x);
        smT[d + 1][jl] = __float2bfloat16(v.y);
        smT[d + 2][jl] = __float2bfloat16(v.z);
        smT[d + 3][jl] = __float2bfloat16(v.w);
    }
    __syncthreads();
    int d = t >> 1;
    int jh = (t & 1) * 32;
    uint4* dst = (uint4*)(g_ST + (size_t)blockIdx.x * (128 * 64) + d * 64 + jh);
    const uint4* s4 = (const uint4*)&smT[d][jh];
    dst[0] = s4[0]; dst[1] = s4[1]; dst[2] = s4[2]; dst[3] = s4[3];
}

// ---------------- kernel 3: warp-specialized fused softmax-GEMM -------------
// grid 128 (64 row-tiles x 2 k-halves), 512 threads.
// warps 0-7: consumers (ldmatrix + mma).  warps 8-15: producers (coalesced adj
// stream, exp, smem ring fill, per-row Z accumulation).
// smem layout:
//   [0, 32768)          sproj half (8192 floats)
//   [32768, 32816)      mbarriers: {full[s], empty[s]} interleaved, s<3
//   [33536 + s*36864)   stage s: A tile 18432B (128 x 144B), B tile 18432B
#define SP_OFF   0
#define BAR_OFF  32768
#define ST_OFF   33536
#define STAGE_SZ 36864
#define A_SZ     18432
#define NSTAGE   3
#define SMEM_BYTES (ST_OFF + NSTAGE * STAGE_SZ)

__global__ void __launch_bounds__(512, 1)
main_kernel(const float* __restrict__ adj) {
    extern __shared__ char smem[];
    const int tid = threadIdx.x;
    const int wid = tid >> 5;
    const int lid = tid & 31;

    const int tile = blockIdx.x >> 1;
    const int kv_half = blockIdx.x & 1;
    const int i0 = tile * 128;
    const int k0 = kv_half * (NSEVT / 2);

    const uint32_t sb = smem_u32(smem);

    // cooperative sproj load (all 512 threads)
    {
        float4* spd = (float4*)(smem + SP_OFF);
        const float4* sps = (const float4*)(g_sproj + k0);
        for (int i = tid; i < 2048; i += 512) spd[i] = __ldg(sps + i);
    }
    if (tid == 0) {
        #pragma unroll
        for (int s = 0; s < NSTAGE; ++s) {
            mbar_init(sb + BAR_OFF + s * 16, 256);      // full[s]: 256 producers
            mbar_init(sb + BAR_OFF + s * 16 + 8, 256);  // empty[s]: 256 consumers
        }
    }
    __syncthreads();

    if (wid >= 8) {
        // =================== PRODUCER (coalesced) ===================
        const int pw = wid - 8;          // 0..7
        const int ptid = tid - 256;      // 0..255
        const int h = lid >> 4;          // half-warp
        const int c4 = lid & 15;         // float4 column slot within 64-col tile
        const int rbase = pw * 2 + h;    // row for iteration i=0 (rows: i*16+rbase)

        // adj: iteration i, tile kt -> a4p + i*65536 + kt*16 (float4 units)
        const float4* a4p = (const float4*)(adj + (size_t)(i0 + rbase) * NSEVT + k0) + c4;
        // B tile source: lane-contiguous bytes
        const char* gstb = (const char*)g_ST + (size_t)(kv_half * 128) * 16384 + ptid * 16;
        const float4* sp4 = (const float4*)(smem + SP_OFF);

        // per-row state (rows fixed across tiles)
        float epArr[8];
        float zrow[8];
        #pragma unroll
        for (int i = 0; i < 8; ++i) {
            epArr[i] = g_eproj[i0 + i * 16 + rbase];
            zrow[i] = 0.f;
        }

        // B smem store addressing: thread's 16B chunk j lands at
        //   (ptid>>3 + j*32)*144 + (ptid&7)*16
        const uint32_t bst_base = (uint32_t)(ptid >> 3) * 144u + (uint32_t)(ptid & 7) * 16u;
        // A smem store addressing: iteration i at (i*16+rbase)*144 + c4*8
        const uint32_t ast_base = (uint32_t)rbase * 144u + (uint32_t)c4 * 8u;

        float4 areg[8];
        #pragma unroll
        for (int i = 0; i < 8; ++i) areg[i] = __ldg(a4p + (size_t)i * 65536);

        int st = 0, ph = 1;   // producer parity starts at 1: first empty-wait passes

        for (int kt = 0; kt < 128; ++kt) {
            // B tile loads (lane-contiguous, 4 wf per instr)
            uint4 bv[4];
            {
                const char* bsrc = gstb + (size_t)kt * 16384;
                #pragma unroll
                for (int j = 0; j < 4; ++j)
                    bv[j] = __ldg((const uint4*)(bsrc + j * 4096));
            }

            // sproj float4 for this tile (broadcast across half-warps)
            float4 s = sp4[kt * 16 + c4];

            // exp compute into wpk (consumes areg), accumulate per-row Z
            uint2 wpk[8];
            #pragma unroll
            for (int i = 0; i < 8; ++i) {
                float4 a = areg[i];
                float ep = epArr[i];
                float c0 = ep + s.x, c1 = ep + s.y, c2 = ep + s.z, c3 = ep + s.w;
                float f0 = fmaxf(c0, 0.2f * c0), f1 = fmaxf(c1, 0.2f * c1);
                float f2 = fmaxf(c2, 0.2f * c2), f3 = fmaxf(c3, 0.2f * c3);
                float e0 = ex2f(a.x * f0), e1 = ex2f(a.y * f1);
                float e2 = ex2f(a.z * f2), e3 = ex2f(a.w * f3);
                zrow[i] += (e0 + e1) + (e2 + e3);
                wpk[i].x = pack_bf16x2(e0 * a.x, e1 * a.y);
                wpk[i].y = pack_bf16x2(e2 * a.z, e3 * a.w);
            }

            // prefetch next adj tile (areg free now)
            if (kt < 127) {
                const float4* anext = a4p + (kt + 1) * 16;
                #pragma unroll
                for (int i = 0; i < 8; ++i) areg[i] = __ldg(anext + (size_t)i * 65536);
            }

            // wait for stage free, store A + B, publish
            mbar_wait(sb + BAR_OFF + st * 16 + 8, ph);
            {
                char* Ab = smem + ST_OFF + (size_t)st * STAGE_SZ;
                char* Bb = Ab + A_SZ;
                #pragma unroll
                for (int i = 0; i < 8; ++i)
                    *reinterpret_cast<uint2*>(Ab + ast_base + i * (16 * 144)) = wpk[i];
                #pragma unroll
                for (int j = 0; j < 4; ++j)
                    *reinterpret_cast<uint4*>(Bb + bst_base + j * (32 * 144)) = bv[j];
            }
            mbar_arrive(sb + BAR_OFF + st * 16);   // full[st]

            if (++st == NSTAGE) { st = 0; ph ^= 1; }
        }

        // Z: reduce across 16-lane column groups, one row per group
        #pragma unroll
        for (int i = 0; i < 8; ++i) {
            float z = zrow[i];
            z += __shfl_xor_sync(0xffffffffu, z, 8);
            z += __shfl_xor_sync(0xffffffffu, z, 4);
            z += __shfl_xor_sync(0xffffffffu, z, 2);
            z += __shfl_xor_sync(0xffffffffu, z, 1);
            if (c4 == 0)
                g_z[(size_t)kv_half * NEVT + i0 + i * 16 + rbase] = z;
        }

    } else {
        // =================== CONSUMER (identical to R5) ===================
        const int m0 = (wid & 3) * 32;
        const int n0 = (wid >> 2) * 64;
        const uint32_t a_radd = (uint32_t)(lid & 15) * 144u + ((uint32_t)(lid >> 4) * 8u) * 2u;
        const uint32_t b_radd = ((uint32_t)(lid & 7) + ((uint32_t)(lid >> 4) & 1u) * 8u) * 144u
                              + (((uint32_t)(lid >> 3) & 1u) * 8u) * 2u;

        float acc[2][8][4];
        #pragma unroll
        for (int mt = 0; mt < 2; ++mt)
            #pragma unroll
            for (int nb = 0; nb < 8; ++nb)
                #pragma unroll
                for (int q = 0; q < 4; ++q) acc[mt][nb][q] = 0.f;

        int st = 0, ph = 0;

        for (int kt = 0; kt < 128; ++kt) {
            mbar_wait(sb + BAR_OFF + st * 16, ph);   // full[st]

            const uint32_t Asb = sb + ST_OFF + (uint32_t)st * STAGE_SZ;
            const uint32_t Bsb = Asb + A_SZ;
            #pragma unroll
            for (int ks = 0; ks < 4; ++ks) {
                uint32_t afr[2][4];
                ldm_x4(Asb + (uint32_t)(m0)      * 144u + (uint32_t)(ks * 16) * 2u + a_radd, afr[0]);
                ldm_x4(Asb + (uint32_t)(m0 + 16) * 144u + (uint32_t)(ks * 16) * 2u + a_radd, afr[1]);
                uint32_t bfr[8][2];
                #pragma unroll
                for (int q = 0; q < 4; ++q) {
                    uint32_t t[4];
                    ldm_x4(Bsb + (uint32_t)(n0 + 16 * q) * 144u + (uint32_t)(ks * 16) * 2u + b_radd, t);
                    bfr[2 * q][0] = t[0]; bfr[2 * q][1] = t[1];
                    bfr[2 * q + 1][0] = t[2]; bfr[2 * q + 1][1] = t[3];
                }
                #pragma unroll
                for (int mt = 0; mt < 2; ++mt)
                    #pragma unroll
                    for (int nb = 0; nb < 8; ++nb)
                        mma16816(acc[mt][nb], afr[mt], bfr[nb]);
            }

            mbar_arrive(sb + BAR_OFF + st * 16 + 8);  // empty[st]
            if (++st == NSTAGE) { st = 0; ph ^= 1; }
        }

        // numerator partial writeout
        float* base = g_num + (size_t)kv_half * NEVT * DIM;
        const int r01 = i0 + m0 + (lid >> 2);
        const int colb = n0 + (lid & 3) * 2;
        #pragma unroll
        for (int mt = 0; mt < 2; ++mt) {
            #pragma unroll
            for (int nb = 0; nb < 8; ++nb) {
                int rr = r01 + mt * 16;
                int cc = colb + nb * 8;
                float2 lo = make_float2(acc[mt][nb][0], acc[mt][nb][1]);
                float2 hi = make_float2(acc[mt][nb][2], acc[mt][nb][3]);
                *reinterpret_cast<float2*>(base + (size_t)rr * DIM + cc) = lo;
                *reinterpret_cast<float2*>(base + (size_t)(rr + 8) * DIM + cc) = hi;
            }
        }
    }
}

// ---------------- kernel 4: combine split-K + epilogue ----------------------
__global__ void finalize_kernel(const float* __restrict__ evt, float* __restrict__ out) {
    int idx = blockIdx.x * blockDim.x + threadIdx.x;   // float4 index
    if (idx >= NEVT * (DIM / 4)) return;
    int i = idx >> 5;                                   // row
    float z = g_z[i] + g_z[NEVT + i];
    float inv = 1.0f / z;
    float4 n0 = *((const float4*)g_num + idx);
    float4 n1 = *((const float4*)g_num + (size_t)NEVT * (DIM / 4) + idx);
    float4 e = __ldg((const float4*)evt + idx);
    float4 o;
    o.x = (e.x + (n0.x + n1.x) * inv) * 0.5f;
    o.y = (e.y + (n0.y + n1.y) * inv) * 0.5f;
    o.z = (e.z + (n0.z + n1.z) * inv) * 0.5f;
    o.w = (e.w + (n0.w + n1.w) * inv) * 0.5f;
    ((float4*)out)[idx] = o;
}

// ---------------- launch ----------------------------------------------------
extern "C" void kernel_launch(void* const* d_in, const int* in_sizes, int n_in,
                              void* d_out, int out_size) {
    const float *adj = nullptr, *sub = nullptr, *evt = nullptr, *w = nullptr;
    for (int i = 0; i < n_in; ++i) {
        switch (in_sizes[i]) {
            case NEVT * NSEVT: adj = (const float*)d_in[i]; break;
            case NSEVT * DIM:  sub = (const float*)d_in[i]; break;
            case NEVT * DIM:   evt = (const float*)d_in[i]; break;
            case 2 * DIM:      w   = (const float*)d_in[i]; break;
            default: break;
        }
    }
    (void)out_size;

    static int configured = 0;
    if (!configured) {
        cudaFuncSetAttribute(main_kernel, cudaFuncAttributeMaxDynamicSharedMemorySize,
                             SMEM_BYTES);
        configured = 1;
    }

    proj_kernel<<<96, 256>>>(sub, evt, w);
    transpose_kernel<<<256, 256>>>(sub);
    main_kernel<<<128, 512, SMEM_BYTES>>>(adj);
    finalize_kernel<<<(NEVT * (DIM / 4) + 255) / 256, 256>>>(evt, (float*)d_out);
}